// round 6
// baseline (speedup 1.0000x reference)
#include <cuda_runtime.h>
#include <math.h>
#include <stdint.h>

#define BATCH 2
#define SEQ   2048
#define DM    1024
#define NH    16
#define HD    64
#define HALF  256

// ---------------- scratch ----------------
__device__ float g_qkv[BATCH * SEQ * 3 * DM];   // [B,N,3,H,Dh] natural, tf32
__device__ float g_attn[BATCH * SEQ * DM];      // [B,N,C] K16-PERMUTED, tf32
__device__ float g_xr[BATCH * SEQ * DM];        // x K16-PERMUTED, tf32
__device__ float g_wqkvT[3 * DM * DM];          // [3C,C] transposed, K16-PERM
__device__ float g_wprojT[DM * DM];             // [C,C]  transposed, K16-PERM

// ---------------- helpers ----------------
__device__ __forceinline__ float tf32r(float x) {
    uint32_t u; asm("cvt.rna.tf32.f32 %0, %1;" : "=r"(u) : "f"(x));
    return __uint_as_float(u);
}
// K16 permutation (self-inverse): pos(k) = (k&3)*4 + (k>>2) within 16-blocks
__device__ __forceinline__ int perm16(int c) {
    int w = c & 15;
    return (c & ~15) | ((w & 3) * 4 + (w >> 2));
}
__device__ __forceinline__ uint32_t smem_u32(const void* p) {
    uint32_t a;
    asm("{ .reg .u64 t; cvta.to.shared.u64 t, %1; cvt.u32.u64 %0, t; }"
        : "=r"(a) : "l"(p));
    return a;
}
__device__ __forceinline__ void cpa16(uint32_t dst, const void* src) {
    asm volatile("cp.async.cg.shared.global [%0], [%1], 16;"
                 :: "r"(dst), "l"(src));
}
#define CP_COMMIT() asm volatile("cp.async.commit_group;" ::: "memory")
#define CP_WAIT(n)  asm volatile("cp.async.wait_group %0;" :: "n"(n) : "memory")

__device__ __forceinline__ void mma_tf32(float* c, const uint32_t* a,
                                         const uint32_t* b) {
    asm volatile(
        "mma.sync.aligned.m16n8k8.row.col.f32.tf32.tf32.f32 "
        "{%0,%1,%2,%3}, {%4,%5,%6,%7}, {%8,%9}, {%0,%1,%2,%3};"
        : "+f"(c[0]), "+f"(c[1]), "+f"(c[2]), "+f"(c[3])
        : "r"(a[0]), "r"(a[1]), "r"(a[2]), "r"(a[3]), "r"(b[0]), "r"(b[1]));
}

// ---------------- prep kernels (K16-permuted writers) ----------------
// 16-float block [k0..k15] -> stored [k0,k4,k8,k12, k1,k5,k9,k13, ...]
__global__ void round_perm_tf32_kernel(const float4* __restrict__ in,
                                       float4* __restrict__ out, int n16) {
    int i = blockIdx.x * blockDim.x + threadIdx.x;
    if (i < n16) {
        float4 a = in[4 * i], b = in[4 * i + 1],
               c = in[4 * i + 2], d = in[4 * i + 3];
        out[4 * i]     = make_float4(tf32r(a.x), tf32r(b.x), tf32r(c.x), tf32r(d.x));
        out[4 * i + 1] = make_float4(tf32r(a.y), tf32r(b.y), tf32r(c.y), tf32r(d.y));
        out[4 * i + 2] = make_float4(tf32r(a.z), tf32r(b.z), tf32r(c.z), tf32r(d.z));
        out[4 * i + 3] = make_float4(tf32r(a.w), tf32r(b.w), tf32r(c.w), tf32r(d.w));
    }
}

// in [R,C] -> out [C,R], out-col (K dim) permuted within 16-blocks
__global__ void transpose_perm_tf32_kernel(const float* __restrict__ in,
                                           float* __restrict__ out,
                                           int R, int C) {
    __shared__ float t[32][33];
    const int c0 = blockIdx.x * 32, r0 = blockIdx.y * 32;
    const int tx = threadIdx.x, ty = threadIdx.y;
    #pragma unroll
    for (int i = 0; i < 32; i += 8)
        t[ty + i][tx] = tf32r(in[(size_t)(r0 + ty + i) * C + c0 + tx]);
    __syncthreads();
    const int pp = perm16(tx);
    #pragma unroll
    for (int i = 0; i < 32; i += 8)
        out[(size_t)(c0 + ty + i) * R + r0 + pp] = t[tx][ty + i];
}

// ---------------- tf32 mma.sync GEMM, 128x256 CTA, LDS.128 fragments ------
#define BM 128
#define BN 256
#define BK 32
#define LDK 40
#define A_FLOATS (BM * LDK)                 // 5120
#define B_FLOATS (BN * LDK)                 // 10240
#define STAGE_FLOATS (A_FLOATS + B_FLOATS)  // 15360
#define GSTAGES 3
#define GEMM_SMEM (GSTAGES * STAGE_FLOATS * 4)   // 184320

__global__ void __launch_bounds__(256, 1)
gemm_mma_kernel(const float* __restrict__ A, const float* __restrict__ BT,
                float* __restrict__ C, const float* __restrict__ bias,
                int M, int N, int K, int round_out)
{
    extern __shared__ float smem[];

    const int tid = threadIdx.x;
    const int wid = tid >> 5, lid = tid & 31;
    const int wm = wid >> 2;            // 0..1  (64 rows)
    const int wn = wid & 3;             // 0..3  (64 cols)
    const int g = lid >> 2, t = lid & 3;
    const int m0 = blockIdx.y * BM, n0 = blockIdx.x * BN;

    const float* Ab = A + (size_t)m0 * K;
    const float* Bb = BT + (size_t)n0 * K;
    const int NC = K / BK;              // 32

    const uint32_t sbase = smem_u32(smem);
    auto load_chunk = [&](int k0, int slot) {
        const uint32_t st = sbase + (uint32_t)(slot * STAGE_FLOATS * 4);
        const uint32_t bb = st + A_FLOATS * 4;
        #pragma unroll
        for (int i = 0; i < 4; i++) {       // A: 128 rows x 8 x 16B
            int idx = tid + i * 256;
            int r = idx >> 3, c16 = idx & 7;
            cpa16(st + (uint32_t)(r * 160 + c16 * 16),
                  Ab + (size_t)r * K + k0 + c16 * 4);
        }
        #pragma unroll
        for (int i = 0; i < 8; i++) {       // B: 256 rows x 8 x 16B
            int idx = tid + i * 256;
            int r = idx >> 3, c16 = idx & 7;
            cpa16(bb + (uint32_t)(r * 160 + c16 * 16),
                  Bb + (size_t)r * K + k0 + c16 * 4);
        }
    };

    float acc[4][8][4];
    #pragma unroll
    for (int i = 0; i < 4; i++)
        #pragma unroll
        for (int j = 0; j < 8; j++)
            #pragma unroll
            for (int r = 0; r < 4; r++) acc[i][j][r] = 0.f;

    load_chunk(0, 0); CP_COMMIT();
    load_chunk(BK, 1); CP_COMMIT();

    int slot_use = 0, slot_load = 2;
    for (int c = 0; c < NC; c++) {
        CP_WAIT(1);
        __syncthreads();
        if (c + 2 < NC) {
            load_chunk((c + 2) * BK, slot_load);
            slot_load = (slot_load + 1 == GSTAGES) ? 0 : slot_load + 1;
        }
        CP_COMMIT();

        const float* As = smem + slot_use * STAGE_FLOATS;
        const float* Bs = As + A_FLOATS;
        slot_use = (slot_use + 1 == GSTAGES) ? 0 : slot_use + 1;

        #pragma unroll
        for (int h16 = 0; h16 < 2; h16++) {    // two 16-k halves of the chunk
            const int fo = h16 * 16 + t * 4;
            float4 av[4][2], bv[8];
            #pragma unroll
            for (int mt = 0; mt < 4; mt++) {
                const int rb = (wm * 64 + mt * 16 + g) * LDK;
                av[mt][0] = *(const float4*)&As[rb + fo];
                av[mt][1] = *(const float4*)&As[rb + 8 * LDK + fo];
            }
            #pragma unroll
            for (int nt = 0; nt < 8; nt++)
                bv[nt] = *(const float4*)&Bs[(wn * 64 + nt * 8 + g) * LDK + fo];

            // k-group 0 of this half: fragments (.x, .y)
            #pragma unroll
            for (int mt = 0; mt < 4; mt++) {
                uint32_t af[4];
                af[0] = __float_as_uint(av[mt][0].x);
                af[1] = __float_as_uint(av[mt][1].x);
                af[2] = __float_as_uint(av[mt][0].y);
                af[3] = __float_as_uint(av[mt][1].y);
                #pragma unroll
                for (int nt = 0; nt < 8; nt++) {
                    uint32_t bf[2] = { __float_as_uint(bv[nt].x),
                                       __float_as_uint(bv[nt].y) };
                    mma_tf32(acc[mt][nt], af, bf);
                }
            }
            // k-group 1 of this half: fragments (.z, .w)
            #pragma unroll
            for (int mt = 0; mt < 4; mt++) {
                uint32_t af[4];
                af[0] = __float_as_uint(av[mt][0].z);
                af[1] = __float_as_uint(av[mt][1].z);
                af[2] = __float_as_uint(av[mt][0].w);
                af[3] = __float_as_uint(av[mt][1].w);
                #pragma unroll
                for (int nt = 0; nt < 8; nt++) {
                    uint32_t bf[2] = { __float_as_uint(bv[nt].z),
                                       __float_as_uint(bv[nt].w) };
                    mma_tf32(acc[mt][nt], af, bf);
                }
            }
        }
    }

    // epilogue (natural N columns)
    float* Cb = C + (size_t)m0 * N + n0;
    #pragma unroll
    for (int mt = 0; mt < 4; mt++) {
        const int r0 = wm * 64 + mt * 16 + g;
        #pragma unroll
        for (int nt = 0; nt < 8; nt++) {
            const int col = wn * 64 + nt * 8 + t * 2;
            float b0 = 0.f, b1 = 0.f;
            if (bias) { b0 = bias[n0 + col]; b1 = bias[n0 + col + 1]; }
            float2 v0 = make_float2(acc[mt][nt][0] + b0, acc[mt][nt][1] + b1);
            float2 v1 = make_float2(acc[mt][nt][2] + b0, acc[mt][nt][3] + b1);
            if (round_out) {
                v0.x = tf32r(v0.x); v0.y = tf32r(v0.y);
                v1.x = tf32r(v1.x); v1.y = tf32r(v1.y);
            }
            *(float2*)(Cb + (size_t)r0 * N + col) = v0;
            *(float2*)(Cb + (size_t)(r0 + 8) * N + col) = v1;
        }
    }
}

// ---------------------------------------------------------------------------
// Banded flash attention on mma.sync tf32 (epilogue writes K16-permuted).
// ---------------------------------------------------------------------------
#define ALD 68
#define ATT_SMEM (6 * 64 * ALD * 4)

__global__ void __launch_bounds__(128) attn_mma_kernel(
    const float* __restrict__ qkv, float* __restrict__ out)
{
    extern __shared__ float sm[];
    float* Qs = sm;
    float* Ks = Qs + 64 * ALD;
    float* Vt = Ks + 2 * 64 * ALD;
    float* Ss = Vt + 2 * 64 * ALD;

    const int tid = threadIdx.x;
    const int w = tid >> 5, lane = tid & 31;
    const int g = lane >> 2, t = lane & 3;
    const int n0 = blockIdx.x * 64;
    const int h  = blockIdx.y;
    const int b  = blockIdx.z;
    const float scale = 0.125f;

    const float* base = qkv + (size_t)b * SEQ * 3 * DM + h * HD;

    const int jlo = max(0, n0 - HALF);
    const int jhi = min(SEQ, n0 + 64 + HALF);
    const int NT = (jhi - jlo) >> 6;

    const uint32_t sQ = smem_u32(Qs);
    const uint32_t sK = smem_u32(Ks);

    {
        #pragma unroll
        for (int i = 0; i < 8; i++) {
            int idx = tid + i * 128;
            int r = idx >> 4, c4 = (idx & 15) * 4;
            uint32_t off = (uint32_t)(r * ALD + c4) * 4;
            cpa16(sQ + off, base + (size_t)(n0 + r) * 3 * DM + c4);
            cpa16(sK + off, base + (size_t)(jlo + r) * 3 * DM + DM + c4);
        }
        CP_COMMIT();
    }

    float4 vr[2][4];
    {
        const float* vb = base + 2 * DM + 16 * w;
        #pragma unroll
        for (int jb = 0; jb < 2; jb++)
            #pragma unroll
            for (int i = 0; i < 4; i++)
                vr[jb][i] = *(const float4*)(vb +
                    (size_t)(jlo + jb * 32 + lane) * 3 * DM + 4 * i);
    }

    float o[8][4];
    #pragma unroll
    for (int dt = 0; dt < 8; dt++)
        #pragma unroll
        for (int r = 0; r < 4; r++) o[dt][r] = 0.f;
    float m0 = -INFINITY, m1 = -INFINITY, l0 = 0.f, l1 = 0.f;

    const int rowA0 = (w * 16 + g) * ALD;
    const int rowA1 = rowA0 + 8 * ALD;
    const int i0 = n0 + w * 16 + g;
    const int i1 = i0 + 8;

    for (int c = 0; c < NT; c++) {
        const int j0 = jlo + c * 64;
        CP_WAIT(0);
        {
            float* vbuf = Vt + (c & 1) * 64 * ALD;
            #pragma unroll
            for (int jb = 0; jb < 2; jb++)
                #pragma unroll
                for (int i = 0; i < 4; i++) {
                    const int d = 16 * w + 4 * i;
                    const int j = jb * 32 + lane;
                    vbuf[(d + 0) * ALD + j] = vr[jb][i].x;
                    vbuf[(d + 1) * ALD + j] = vr[jb][i].y;
                    vbuf[(d + 2) * ALD + j] = vr[jb][i].z;
                    vbuf[(d + 3) * ALD + j] = vr[jb][i].w;
                }
        }
        __syncthreads();

        if (c + 1 < NT) {
            const uint32_t kb = sK + (uint32_t)(((c + 1) & 1) * 64 * ALD * 4);
            #pragma unroll
            for (int i = 0; i < 8; i++) {
                int idx = tid + i * 128;
                int r = idx >> 4, c4 = (idx & 15) * 4;
                cpa16(kb + (uint32_t)(r * ALD + c4) * 4,
                      base + (size_t)(j0 + 64 + r) * 3 * DM + DM + c4);
            }
            CP_COMMIT();
            const float* vb = base + 2 * DM + 16 * w;
            #pragma unroll
            for (int jb = 0; jb < 2; jb++)
                #pragma unroll
                for (int i = 0; i < 4; i++)
                    vr[jb][i] = *(const float4*)(vb +
                        (size_t)(j0 + 64 + jb * 32 + lane) * 3 * DM + 4 * i);
        }

        float s[8][4];
        #pragma unroll
        for (int nt = 0; nt < 8; nt++)
            #pragma unroll
            for (int r = 0; r < 4; r++) s[nt][r] = 0.f;

        const float* kbuf = Ks + (c & 1) * 64 * ALD;
        #pragma unroll
        for (int ks = 0; ks < 8; ks++) {
            const int kk = ks * 8;
            uint32_t af[4];
            af[0] = __float_as_uint(Qs[rowA0 + kk + t]);
            af[1] = __float_as_uint(Qs[rowA1 + kk + t]);
            af[2] = __float_as_uint(Qs[rowA0 + kk + t + 4]);
            af[3] = __float_as_uint(Qs[rowA1 + kk + t + 4]);
            #pragma unroll
            for (int nt = 0; nt < 8; nt++) {
                uint32_t bf[2];
                const float* kp = kbuf + (8 * nt + g) * ALD + kk + t;
                bf[0] = __float_as_uint(kp[0]);
                bf[1] = __float_as_uint(kp[4]);
                mma_tf32(s[nt], af, bf);
            }
        }

        const bool masked = (j0 - n0 == HALF) || (n0 - j0 == HALF);
        #pragma unroll
        for (int nt = 0; nt < 8; nt++) {
            #pragma unroll
            for (int r = 0; r < 4; r++) s[nt][r] *= scale;
            if (masked) {
                const int jc = j0 + 8 * nt + 2 * t;
                if (abs(i0 - jc) > HALF)       s[nt][0] = -INFINITY;
                if (abs(i0 - (jc + 1)) > HALF) s[nt][1] = -INFINITY;
                if (abs(i1 - jc) > HALF)       s[nt][2] = -INFINITY;
                if (abs(i1 - (jc + 1)) > HALF) s[nt][3] = -INFINITY;
            }
        }
        float mx0 = -INFINITY, mx1 = -INFINITY;
        #pragma unroll
        for (int nt = 0; nt < 8; nt++) {
            mx0 = fmaxf(mx0, fmaxf(s[nt][0], s[nt][1]));
            mx1 = fmaxf(mx1, fmaxf(s[nt][2], s[nt][3]));
        }
        mx0 = fmaxf(mx0, __shfl_xor_sync(0xffffffffu, mx0, 1));
        mx0 = fmaxf(mx0, __shfl_xor_sync(0xffffffffu, mx0, 2));
        mx1 = fmaxf(mx1, __shfl_xor_sync(0xffffffffu, mx1, 1));
        mx1 = fmaxf(mx1, __shfl_xor_sync(0xffffffffu, mx1, 2));
        const float nm0 = fmaxf(m0, mx0), nm1 = fmaxf(m1, mx1);
        const float corr0 = __expf(m0 - nm0), corr1 = __expf(m1 - nm1);
        m0 = nm0; m1 = nm1;

        float sum0 = 0.f, sum1 = 0.f;
        #pragma unroll
        for (int nt = 0; nt < 8; nt++) {
            s[nt][0] = __expf(s[nt][0] - nm0);
            s[nt][1] = __expf(s[nt][1] - nm0);
            s[nt][2] = __expf(s[nt][2] - nm1);
            s[nt][3] = __expf(s[nt][3] - nm1);
            sum0 += s[nt][0] + s[nt][1];
            sum1 += s[nt][2] + s[nt][3];
            float* sp = Ss + rowA0 + 8 * nt + 2 * t;
            *(float2*)sp = make_float2(s[nt][0], s[nt][1]);
            *(float2*)(sp + 8 * ALD) = make_float2(s[nt][2], s[nt][3]);
        }
        sum0 += __shfl_xor_sync(0xffffffffu, sum0, 1);
        sum0 += __shfl_xor_sync(0xffffffffu, sum0, 2);
        sum1 += __shfl_xor_sync(0xffffffffu, sum1, 1);
        sum1 += __shfl_xor_sync(0xffffffffu, sum1, 2);
        l0 = l0 * corr0 + sum0;
        l1 = l1 * corr1 + sum1;
        #pragma unroll
        for (int dt = 0; dt < 8; dt++) {
            o[dt][0] *= corr0; o[dt][1] *= corr0;
            o[dt][2] *= corr1; o[dt][3] *= corr1;
        }
        __syncwarp();

        const float* vbuf = Vt + (c & 1) * 64 * ALD;
        #pragma unroll
        for (int ks = 0; ks < 8; ks++) {
            const int kk = ks * 8;
            uint32_t af[4];
            af[0] = __float_as_uint(Ss[rowA0 + kk + t]);
            af[1] = __float_as_uint(Ss[rowA1 + kk + t]);
            af[2] = __float_as_uint(Ss[rowA0 + kk + t + 4]);
            af[3] = __float_as_uint(Ss[rowA1 + kk + t + 4]);
            #pragma unroll
            for (int dt = 0; dt < 8; dt++) {
                uint32_t bf[2];
                const float* vp = vbuf + (8 * dt + g) * ALD + kk + t;
                bf[0] = __float_as_uint(vp[0]);
                bf[1] = __float_as_uint(vp[4]);
                mma_tf32(o[dt], af, bf);
            }
        }
    }

    // epilogue: normalize + tf32 + K16-PERMUTED store
    const float inv0 = 1.f / l0, inv1 = 1.f / l1;
    float* o0 = out + ((size_t)(b * SEQ + i0)) * DM + h * HD;
    float* o1 = o0 + (size_t)8 * DM;
    #pragma unroll
    for (int dt = 0; dt < 8; dt++) {
        const int cn = 8 * dt + 2 * t;
        const int p0 = perm16(cn), p1 = perm16(cn + 1);
        o0[p0] = tf32r(o[dt][0] * inv0);
        o0[p1] = tf32r(o[dt][1] * inv0);
        o1[p0] = tf32r(o[dt][2] * inv1);
        o1[p1] = tf32r(o[dt][3] * inv1);
    }
}

// ---------------------------------------------------------------------------
extern "C" void kernel_launch(void* const* d_in, const int* in_sizes, int n_in,
                              void* d_out, int out_size)
{
    const float* x     = (const float*)d_in[0];
    const float* Wqkv  = (const float*)d_in[1];
    const float* Wproj = (const float*)d_in[2];
    const float* bproj = (const float*)d_in[3];
    float* out = (float*)d_out;

    float *qkv, *attn, *xr, *wqkvT, *wprojT;
    cudaGetSymbolAddress((void**)&qkv, g_qkv);
    cudaGetSymbolAddress((void**)&attn, g_attn);
    cudaGetSymbolAddress((void**)&xr, g_xr);
    cudaGetSymbolAddress((void**)&wqkvT, g_wqkvT);
    cudaGetSymbolAddress((void**)&wprojT, g_wprojT);

    const int M = BATCH * SEQ;
    cudaFuncSetAttribute(attn_mma_kernel,
                         cudaFuncAttributeMaxDynamicSharedMemorySize,
                         ATT_SMEM);
    cudaFuncSetAttribute(gemm_mma_kernel,
                         cudaFuncAttributeMaxDynamicSharedMemorySize,
                         GEMM_SMEM);

    // 0) prep (all GEMM K-operands stored K16-permuted)
    {
        const int n16 = M * DM / 16;
        round_perm_tf32_kernel<<<(n16 + 255) / 256, 256>>>(
            (const float4*)x, (float4*)xr, n16);
        dim3 tb(32, 8);
        transpose_perm_tf32_kernel<<<dim3(3 * DM / 32, DM / 32), tb>>>(
            Wqkv, wqkvT, DM, 3 * DM);
        transpose_perm_tf32_kernel<<<dim3(DM / 32, DM / 32), tb>>>(
            Wproj, wprojT, DM, DM);
    }
    // 1) QKV projection (natural output, tf32-rounded for attention)
    {
        dim3 grid(3 * DM / BN, M / BM);   // (12, 32)
        gemm_mma_kernel<<<grid, 256, GEMM_SMEM>>>(xr, wqkvT, qkv, nullptr,
                                                  M, 3 * DM, DM, 1);
    }
    // 2) banded attention (K16-permuted output feeds proj GEMM)
    {
        dim3 grid(SEQ / 64, NH, BATCH);
        attn_mma_kernel<<<grid, 128, ATT_SMEM>>>(qkv, attn);
    }
    // 3) output projection + bias (natural output)
    {
        dim3 grid(DM / BN, M / BM);       // (4, 32)
        gemm_mma_kernel<<<grid, 256, GEMM_SMEM>>>(attn, wprojT, out, bproj,
                                                  M, DM, DM, 0);
    }
}

// round 7
// speedup vs baseline: 1.6514x; 1.6514x over previous
#include <cuda_runtime.h>
#include <cuda_fp16.h>
#include <math.h>
#include <stdint.h>

#define BATCH 2
#define SEQ   2048
#define DM    1024
#define NH    16
#define HD    64
#define HALF  256

// ---------------- scratch ----------------
__device__ float  g_qkv[BATCH * SEQ * 3 * DM];  // [B,N,3,H,Dh] fp32 (tf32-rounded)
__device__ __half g_attnh[BATCH * SEQ * DM];    // attention out, fp16
__device__ __half g_xh[BATCH * SEQ * DM];       // x in fp16
__device__ __half g_wqkvTh[3 * DM * DM];        // [3C,C] transposed fp16
__device__ __half g_wprojTh[DM * DM];           // [C,C] transposed fp16

// ---------------- helpers ----------------
__device__ __forceinline__ float tf32r(float x) {
    uint32_t u; asm("cvt.rna.tf32.f32 %0, %1;" : "=r"(u) : "f"(x));
    return __uint_as_float(u);
}
__device__ __forceinline__ uint32_t smem_u32(const void* p) {
    uint32_t a;
    asm("{ .reg .u64 t; cvta.to.shared.u64 t, %1; cvt.u32.u64 %0, t; }"
        : "=r"(a) : "l"(p));
    return a;
}
__device__ __forceinline__ void cpa16(uint32_t dst, const void* src) {
    asm volatile("cp.async.cg.shared.global [%0], [%1], 16;"
                 :: "r"(dst), "l"(src));
}
#define CP_COMMIT() asm volatile("cp.async.commit_group;" ::: "memory")
#define CP_WAIT(n)  asm volatile("cp.async.wait_group %0;" :: "n"(n) : "memory")

__device__ __forceinline__ void ldsm4(uint32_t& r0, uint32_t& r1,
                                      uint32_t& r2, uint32_t& r3,
                                      uint32_t addr) {
    asm volatile("ldmatrix.sync.aligned.m8n8.x4.shared.b16 {%0,%1,%2,%3}, [%4];"
                 : "=r"(r0), "=r"(r1), "=r"(r2), "=r"(r3) : "r"(addr));
}
__device__ __forceinline__ void mma_f16(float* c, const uint32_t* a,
                                        const uint32_t* b) {
    asm volatile(
        "mma.sync.aligned.m16n8k16.row.col.f32.f16.f16.f32 "
        "{%0,%1,%2,%3}, {%4,%5,%6,%7}, {%8,%9}, {%0,%1,%2,%3};"
        : "+f"(c[0]), "+f"(c[1]), "+f"(c[2]), "+f"(c[3])
        : "r"(a[0]), "r"(a[1]), "r"(a[2]), "r"(a[3]), "r"(b[0]), "r"(b[1]));
}
__device__ __forceinline__ void mma_tf32(float* c, const uint32_t* a,
                                         const uint32_t* b) {
    asm volatile(
        "mma.sync.aligned.m16n8k8.row.col.f32.tf32.tf32.f32 "
        "{%0,%1,%2,%3}, {%4,%5,%6,%7}, {%8,%9}, {%0,%1,%2,%3};"
        : "+f"(c[0]), "+f"(c[1]), "+f"(c[2]), "+f"(c[3])
        : "r"(a[0]), "r"(a[1]), "r"(a[2]), "r"(a[3]), "r"(b[0]), "r"(b[1]));
}

// ---------------- prep kernels ----------------
__global__ void f32_to_f16_kernel(const float4* __restrict__ in,
                                  uint4* __restrict__ out, int n8) {
    int i = blockIdx.x * blockDim.x + threadIdx.x;
    if (i < n8) {
        float4 a = in[2 * i], b = in[2 * i + 1];
        __half2 h0 = __floats2half2_rn(a.x, a.y);
        __half2 h1 = __floats2half2_rn(a.z, a.w);
        __half2 h2 = __floats2half2_rn(b.x, b.y);
        __half2 h3 = __floats2half2_rn(b.z, b.w);
        uint4 o;
        o.x = *(uint32_t*)&h0; o.y = *(uint32_t*)&h1;
        o.z = *(uint32_t*)&h2; o.w = *(uint32_t*)&h3;
        out[i] = o;
    }
}

// in [R,C] fp32 -> out [C,R] fp16
__global__ void transpose_f16_kernel(const float* __restrict__ in,
                                     __half* __restrict__ out, int R, int C) {
    __shared__ float t[32][33];
    const int c0 = blockIdx.x * 32, r0 = blockIdx.y * 32;
    const int tx = threadIdx.x, ty = threadIdx.y;
    #pragma unroll
    for (int i = 0; i < 32; i += 8)
        t[ty + i][tx] = in[(size_t)(r0 + ty + i) * C + c0 + tx];
    __syncthreads();
    #pragma unroll
    for (int i = 0; i < 32; i += 8)
        out[(size_t)(c0 + ty + i) * R + r0 + tx] = __float2half_rn(t[tx][ty + i]);
}

// ---------------- fp16 mma.sync GEMM ----------------
// C[M,N](f32) = A[M,K](f16) @ BT[N,K](f16)^T (+bias).
// CTA 128x128, BK=64, 3 stages, 8 warps (4m x 2n), warp tile 32x64.
#define HLD 72                                   // halves per row (64 + 8 pad)
#define HTILE_B (128 * HLD * 2)                  // 18432 bytes per operand
#define HSTAGE_B (2 * HTILE_B)                   // 36864
#define HSTAGES 3
#define GEMM_SMEM (HSTAGES * HSTAGE_B)           // 110592

__global__ void __launch_bounds__(256, 2)
gemm_f16_kernel(const __half* __restrict__ A, const __half* __restrict__ BT,
                float* __restrict__ C, const float* __restrict__ bias,
                int M, int N, int K, int round_out)
{
    extern __shared__ __half hsm[];
    const uint32_t sbase = smem_u32(hsm);

    const int tid = threadIdx.x;
    const int wid = tid >> 5, lane = tid & 31;
    const int wm = wid >> 1;            // 0..3 (32 rows)
    const int wn = wid & 1;             // 0..1 (64 cols)
    const int g = lane >> 2, t = lane & 3;
    const int q = lane >> 3, rl = lane & 7;
    const int m0 = blockIdx.y * 128, n0 = blockIdx.x * 128;

    const __half* Ab = A + (size_t)m0 * K;
    const __half* Bb = BT + (size_t)n0 * K;
    const int NC = K / 64;              // 16

    auto load_chunk = [&](int k0, int slot) {
        const uint32_t st = sbase + (uint32_t)(slot * HSTAGE_B);
        const uint32_t bb = st + HTILE_B;
        #pragma unroll
        for (int i = 0; i < 4; i++) {       // 128 rows x 8 x 16B per operand
            int idx = tid + i * 256;
            int r = idx >> 3, c16 = idx & 7;
            cpa16(st + (uint32_t)(r * 144 + c16 * 16),
                  Ab + (size_t)r * K + k0 + c16 * 8);
            cpa16(bb + (uint32_t)(r * 144 + c16 * 16),
                  Bb + (size_t)r * K + k0 + c16 * 8);
        }
    };

    // per-lane ldmatrix base offsets (bytes), k advances by 32B per k16
    uint32_t aoff[2], boff[4];
    #pragma unroll
    for (int mt = 0; mt < 2; mt++)
        aoff[mt] = (uint32_t)((wm * 32 + mt * 16 + (q & 1) * 8 + rl) * 144 +
                              (q >> 1) * 16);
    #pragma unroll
    for (int j = 0; j < 4; j++)
        boff[j] = (uint32_t)((wn * 64 + (2 * j + (q >> 1)) * 8 + rl) * 144 +
                             (q & 1) * 16) + HTILE_B;

    float acc[2][8][4];
    #pragma unroll
    for (int i = 0; i < 2; i++)
        #pragma unroll
        for (int j = 0; j < 8; j++)
            #pragma unroll
            for (int r = 0; r < 4; r++) acc[i][j][r] = 0.f;

    load_chunk(0, 0); CP_COMMIT();
    load_chunk(64, 1); CP_COMMIT();

    int slot_use = 0, slot_load = 2;
    for (int c = 0; c < NC; c++) {
        CP_WAIT(1);
        __syncthreads();
        if (c + 2 < NC) {
            load_chunk((c + 2) * 64, slot_load);
            slot_load = (slot_load + 1 == HSTAGES) ? 0 : slot_load + 1;
        }
        CP_COMMIT();

        const uint32_t st = sbase + (uint32_t)(slot_use * HSTAGE_B);
        slot_use = (slot_use + 1 == HSTAGES) ? 0 : slot_use + 1;

        #pragma unroll
        for (int ks = 0; ks < 4; ks++) {
            const uint32_t kadd = st + ks * 32;
            uint32_t a[2][4];
            ldsm4(a[0][0], a[0][1], a[0][2], a[0][3], kadd + aoff[0]);
            ldsm4(a[1][0], a[1][1], a[1][2], a[1][3], kadd + aoff[1]);
            #pragma unroll
            for (int j = 0; j < 4; j++) {
                uint32_t b0, b1, b2, b3;
                ldsm4(b0, b1, b2, b3, kadd + boff[j]);
                uint32_t be[2] = { b0, b1 }, bo[2] = { b2, b3 };
                mma_f16(acc[0][2 * j],     a[0], be);
                mma_f16(acc[1][2 * j],     a[1], be);
                mma_f16(acc[0][2 * j + 1], a[0], bo);
                mma_f16(acc[1][2 * j + 1], a[1], bo);
            }
        }
    }

    // epilogue
    float* Cb = C + (size_t)m0 * N + n0;
    #pragma unroll
    for (int mt = 0; mt < 2; mt++) {
        const int r0 = wm * 32 + mt * 16 + g;
        #pragma unroll
        for (int nt = 0; nt < 8; nt++) {
            const int col = wn * 64 + nt * 8 + t * 2;
            float b0 = 0.f, b1 = 0.f;
            if (bias) { b0 = bias[n0 + col]; b1 = bias[n0 + col + 1]; }
            float2 v0 = make_float2(acc[mt][nt][0] + b0, acc[mt][nt][1] + b1);
            float2 v1 = make_float2(acc[mt][nt][2] + b0, acc[mt][nt][3] + b1);
            if (round_out) {
                v0.x = tf32r(v0.x); v0.y = tf32r(v0.y);
                v1.x = tf32r(v1.x); v1.y = tf32r(v1.y);
            }
            *(float2*)(Cb + (size_t)r0 * N + col) = v0;
            *(float2*)(Cb + (size_t)(r0 + 8) * N + col) = v1;
        }
    }
}

// ---------------------------------------------------------------------------
// Banded flash attention on mma.sync tf32 (round-5 version; fp16 output).
// ---------------------------------------------------------------------------
#define ALD 68
#define ATT_SMEM (6 * 64 * ALD * 4)

__global__ void __launch_bounds__(128) attn_mma_kernel(
    const float* __restrict__ qkv, __half* __restrict__ out)
{
    extern __shared__ float sm[];
    float* Qs = sm;
    float* Ks = Qs + 64 * ALD;
    float* Vt = Ks + 2 * 64 * ALD;
    float* Ss = Vt + 2 * 64 * ALD;

    const int tid = threadIdx.x;
    const int w = tid >> 5, lane = tid & 31;
    const int g = lane >> 2, t = lane & 3;
    const int n0 = blockIdx.x * 64;
    const int h  = blockIdx.y;
    const int b  = blockIdx.z;
    const float scale = 0.125f;

    const float* base = qkv + (size_t)b * SEQ * 3 * DM + h * HD;

    const int jlo = max(0, n0 - HALF);
    const int jhi = min(SEQ, n0 + 64 + HALF);
    const int NT = (jhi - jlo) >> 6;

    const uint32_t sQ = smem_u32(Qs);
    const uint32_t sK = smem_u32(Ks);

    {
        #pragma unroll
        for (int i = 0; i < 8; i++) {
            int idx = tid + i * 128;
            int r = idx >> 4, c4 = (idx & 15) * 4;
            uint32_t off = (uint32_t)(r * ALD + c4) * 4;
            cpa16(sQ + off, base + (size_t)(n0 + r) * 3 * DM + c4);
            cpa16(sK + off, base + (size_t)(jlo + r) * 3 * DM + DM + c4);
        }
        CP_COMMIT();
    }

    float4 vr[2][4];
    {
        const float* vb = base + 2 * DM + 16 * w;
        #pragma unroll
        for (int jb = 0; jb < 2; jb++)
            #pragma unroll
            for (int i = 0; i < 4; i++)
                vr[jb][i] = *(const float4*)(vb +
                    (size_t)(jlo + jb * 32 + lane) * 3 * DM + 4 * i);
    }

    float o[8][4];
    #pragma unroll
    for (int dt = 0; dt < 8; dt++)
        #pragma unroll
        for (int r = 0; r < 4; r++) o[dt][r] = 0.f;
    float m0 = -INFINITY, m1 = -INFINITY, l0 = 0.f, l1 = 0.f;

    const int rowA0 = (w * 16 + g) * ALD;
    const int rowA1 = rowA0 + 8 * ALD;
    const int i0 = n0 + w * 16 + g;
    const int i1 = i0 + 8;

    for (int c = 0; c < NT; c++) {
        const int j0 = jlo + c * 64;
        CP_WAIT(0);
        {
            float* vbuf = Vt + (c & 1) * 64 * ALD;
            #pragma unroll
            for (int jb = 0; jb < 2; jb++)
                #pragma unroll
                for (int i = 0; i < 4; i++) {
                    const int d = 16 * w + 4 * i;
                    const int j = jb * 32 + lane;
                    vbuf[(d + 0) * ALD + j] = vr[jb][i].x;
                    vbuf[(d + 1) * ALD + j] = vr[jb][i].y;
                    vbuf[(d + 2) * ALD + j] = vr[jb][i].z;
                    vbuf[(d + 3) * ALD + j] = vr[jb][i].w;
                }
        }
        __syncthreads();

        if (c + 1 < NT) {
            const uint32_t kb = sK + (uint32_t)(((c + 1) & 1) * 64 * ALD * 4);
            #pragma unroll
            for (int i = 0; i < 8; i++) {
                int idx = tid + i * 128;
                int r = idx >> 4, c4 = (idx & 15) * 4;
                cpa16(kb + (uint32_t)(r * ALD + c4) * 4,
                      base + (size_t)(j0 + 64 + r) * 3 * DM + DM + c4);
            }
            CP_COMMIT();
            const float* vb = base + 2 * DM + 16 * w;
            #pragma unroll
            for (int jb = 0; jb < 2; jb++)
                #pragma unroll
                for (int i = 0; i < 4; i++)
                    vr[jb][i] = *(const float4*)(vb +
                        (size_t)(j0 + 64 + jb * 32 + lane) * 3 * DM + 4 * i);
        }

        float s[8][4];
        #pragma unroll
        for (int nt = 0; nt < 8; nt++)
            #pragma unroll
            for (int r = 0; r < 4; r++) s[nt][r] = 0.f;

        const float* kbuf = Ks + (c & 1) * 64 * ALD;
        #pragma unroll
        for (int ks = 0; ks < 8; ks++) {
            const int kk = ks * 8;
            uint32_t af[4];
            af[0] = __float_as_uint(Qs[rowA0 + kk + t]);
            af[1] = __float_as_uint(Qs[rowA1 + kk + t]);
            af[2] = __float_as_uint(Qs[rowA0 + kk + t + 4]);
            af[3] = __float_as_uint(Qs[rowA1 + kk + t + 4]);
            #pragma unroll
            for (int nt = 0; nt < 8; nt++) {
                uint32_t bf[2];
                const float* kp = kbuf + (8 * nt + g) * ALD + kk + t;
                bf[0] = __float_as_uint(kp[0]);
                bf[1] = __float_as_uint(kp[4]);
                mma_tf32(s[nt], af, bf);
            }
        }

        const bool masked = (j0 - n0 == HALF) || (n0 - j0 == HALF);
        #pragma unroll
        for (int nt = 0; nt < 8; nt++) {
            #pragma unroll
            for (int r = 0; r < 4; r++) s[nt][r] *= scale;
            if (masked) {
                const int jc = j0 + 8 * nt + 2 * t;
                if (abs(i0 - jc) > HALF)       s[nt][0] = -INFINITY;
                if (abs(i0 - (jc + 1)) > HALF) s[nt][1] = -INFINITY;
                if (abs(i1 - jc) > HALF)       s[nt][2] = -INFINITY;
                if (abs(i1 - (jc + 1)) > HALF) s[nt][3] = -INFINITY;
            }
        }
        float mx0 = -INFINITY, mx1 = -INFINITY;
        #pragma unroll
        for (int nt = 0; nt < 8; nt++) {
            mx0 = fmaxf(mx0, fmaxf(s[nt][0], s[nt][1]));
            mx1 = fmaxf(mx1, fmaxf(s[nt][2], s[nt][3]));
        }
        mx0 = fmaxf(mx0, __shfl_xor_sync(0xffffffffu, mx0, 1));
        mx0 = fmaxf(mx0, __shfl_xor_sync(0xffffffffu, mx0, 2));
        mx1 = fmaxf(mx1, __shfl_xor_sync(0xffffffffu, mx1, 1));
        mx1 = fmaxf(mx1, __shfl_xor_sync(0xffffffffu, mx1, 2));
        const float nm0 = fmaxf(m0, mx0), nm1 = fmaxf(m1, mx1);
        const float corr0 = __expf(m0 - nm0), corr1 = __expf(m1 - nm1);
        m0 = nm0; m1 = nm1;

        float sum0 = 0.f, sum1 = 0.f;
        #pragma unroll
        for (int nt = 0; nt < 8; nt++) {
            s[nt][0] = __expf(s[nt][0] - nm0);
            s[nt][1] = __expf(s[nt][1] - nm0);
            s[nt][2] = __expf(s[nt][2] - nm1);
            s[nt][3] = __expf(s[nt][3] - nm1);
            sum0 += s[nt][0] + s[nt][1];
            sum1 += s[nt][2] + s[nt][3];
            float* sp = Ss + rowA0 + 8 * nt + 2 * t;
            *(float2*)sp = make_float2(s[nt][0], s[nt][1]);
            *(float2*)(sp + 8 * ALD) = make_float2(s[nt][2], s[nt][3]);
        }
        sum0 += __shfl_xor_sync(0xffffffffu, sum0, 1);
        sum0 += __shfl_xor_sync(0xffffffffu, sum0, 2);
        sum1 += __shfl_xor_sync(0xffffffffu, sum1, 1);
        sum1 += __shfl_xor_sync(0xffffffffu, sum1, 2);
        l0 = l0 * corr0 + sum0;
        l1 = l1 * corr1 + sum1;
        #pragma unroll
        for (int dt = 0; dt < 8; dt++) {
            o[dt][0] *= corr0; o[dt][1] *= corr0;
            o[dt][2] *= corr1; o[dt][3] *= corr1;
        }
        __syncwarp();

        const float* vbuf = Vt + (c & 1) * 64 * ALD;
        #pragma unroll
        for (int ks = 0; ks < 8; ks++) {
            const int kk = ks * 8;
            uint32_t af[4];
            af[0] = __float_as_uint(Ss[rowA0 + kk + t]);
            af[1] = __float_as_uint(Ss[rowA1 + kk + t]);
            af[2] = __float_as_uint(Ss[rowA0 + kk + t + 4]);
            af[3] = __float_as_uint(Ss[rowA1 + kk + t + 4]);
            #pragma unroll
            for (int dt = 0; dt < 8; dt++) {
                uint32_t bf[2];
                const float* vp = vbuf + (8 * dt + g) * ALD + kk + t;
                bf[0] = __float_as_uint(vp[0]);
                bf[1] = __float_as_uint(vp[4]);
                mma_tf32(o[dt], af, bf);
            }
        }
    }

    // epilogue: normalize + fp16 store (natural layout)
    const float inv0 = 1.f / l0, inv1 = 1.f / l1;
    __half* o0 = out + ((size_t)(b * SEQ + i0)) * DM + h * HD;
    __half* o1 = o0 + (size_t)8 * DM;
    #pragma unroll
    for (int dt = 0; dt < 8; dt++) {
        const int col = 8 * dt + 2 * t;
        *(__half2*)(o0 + col) = __floats2half2_rn(o[dt][0] * inv0,
                                                  o[dt][1] * inv0);
        *(__half2*)(o1 + col) = __floats2half2_rn(o[dt][2] * inv1,
                                                  o[dt][3] * inv1);
    }
}

// ---------------------------------------------------------------------------
extern "C" void kernel_launch(void* const* d_in, const int* in_sizes, int n_in,
                              void* d_out, int out_size)
{
    const float* x     = (const float*)d_in[0];
    const float* Wqkv  = (const float*)d_in[1];
    const float* Wproj = (const float*)d_in[2];
    const float* bproj = (const float*)d_in[3];
    float* out = (float*)d_out;

    float* qkv;
    __half *attnh, *xh, *wqkvTh, *wprojTh;
    cudaGetSymbolAddress((void**)&qkv, g_qkv);
    cudaGetSymbolAddress((void**)&attnh, g_attnh);
    cudaGetSymbolAddress((void**)&xh, g_xh);
    cudaGetSymbolAddress((void**)&wqkvTh, g_wqkvTh);
    cudaGetSymbolAddress((void**)&wprojTh, g_wprojTh);

    const int M = BATCH * SEQ;
    cudaFuncSetAttribute(attn_mma_kernel,
                         cudaFuncAttributeMaxDynamicSharedMemorySize,
                         ATT_SMEM);
    cudaFuncSetAttribute(gemm_f16_kernel,
                         cudaFuncAttributeMaxDynamicSharedMemorySize,
                         GEMM_SMEM);

    // 0) prep: convert x and transposed weights to fp16
    {
        const int n8 = M * DM / 8;
        f32_to_f16_kernel<<<(n8 + 255) / 256, 256>>>(
            (const float4*)x, (uint4*)xh, n8);
        dim3 tb(32, 8);
        transpose_f16_kernel<<<dim3(3 * DM / 32, DM / 32), tb>>>(
            Wqkv, wqkvTh, DM, 3 * DM);
        transpose_f16_kernel<<<dim3(DM / 32, DM / 32), tb>>>(
            Wproj, wprojTh, DM, DM);
    }
    // 1) QKV projection (fp16 tensor cores; fp32 tf32-rounded output)
    {
        dim3 grid(3 * DM / 128, M / 128);   // (24, 32)
        gemm_f16_kernel<<<grid, 256, GEMM_SMEM>>>(xh, wqkvTh, qkv, nullptr,
                                                  M, 3 * DM, DM, 1);
    }
    // 2) banded attention (tf32 tensor cores; fp16 output)
    {
        dim3 grid(SEQ / 64, NH, BATCH);
        attn_mma_kernel<<<grid, 128, ATT_SMEM>>>(qkv, attnh);
    }
    // 3) output projection + bias (fp16 tensor cores; fp32 output)
    {
        dim3 grid(DM / 128, M / 128);       // (8, 32)
        gemm_f16_kernel<<<grid, 256, GEMM_SMEM>>>(attnh, wprojTh, out, bproj,
                                                  M, DM, DM, 0);
    }
}

// round 8
// speedup vs baseline: 2.3307x; 1.4113x over previous
#include <cuda_runtime.h>
#include <cuda_fp16.h>
#include <math.h>
#include <stdint.h>

#define BATCH 2
#define SEQ   2048
#define DM    1024
#define NH    16
#define HD    64
#define HALF  256

// ---------------- scratch ----------------
__device__ __half g_qkvh[BATCH * SEQ * 3 * DM];  // [B,N,3,H,Dh] fp16
__device__ __half g_attnh[BATCH * SEQ * DM];     // attention out, fp16
__device__ __half g_xh[BATCH * SEQ * DM];        // x in fp16
__device__ __half g_wqkvTh[3 * DM * DM];         // [3C,C] transposed fp16
__device__ __half g_wprojTh[DM * DM];            // [C,C] transposed fp16

// ---------------- helpers ----------------
__device__ __forceinline__ uint32_t smem_u32(const void* p) {
    uint32_t a;
    asm("{ .reg .u64 t; cvta.to.shared.u64 t, %1; cvt.u32.u64 %0, t; }"
        : "=r"(a) : "l"(p));
    return a;
}
__device__ __forceinline__ void cpa16(uint32_t dst, const void* src) {
    asm volatile("cp.async.cg.shared.global [%0], [%1], 16;"
                 :: "r"(dst), "l"(src));
}
#define CP_COMMIT() asm volatile("cp.async.commit_group;" ::: "memory")
#define CP_WAIT(n)  asm volatile("cp.async.wait_group %0;" :: "n"(n) : "memory")

__device__ __forceinline__ void ldsm4(uint32_t& r0, uint32_t& r1,
                                      uint32_t& r2, uint32_t& r3,
                                      uint32_t addr) {
    asm volatile("ldmatrix.sync.aligned.m8n8.x4.shared.b16 {%0,%1,%2,%3}, [%4];"
                 : "=r"(r0), "=r"(r1), "=r"(r2), "=r"(r3) : "r"(addr));
}
__device__ __forceinline__ void ldsm4t(uint32_t& r0, uint32_t& r1,
                                       uint32_t& r2, uint32_t& r3,
                                       uint32_t addr) {
    asm volatile("ldmatrix.sync.aligned.m8n8.x4.trans.shared.b16 {%0,%1,%2,%3}, [%4];"
                 : "=r"(r0), "=r"(r1), "=r"(r2), "=r"(r3) : "r"(addr));
}
__device__ __forceinline__ void mma_f16(float* c, const uint32_t* a,
                                        const uint32_t* b) {
    asm volatile(
        "mma.sync.aligned.m16n8k16.row.col.f32.f16.f16.f32 "
        "{%0,%1,%2,%3}, {%4,%5,%6,%7}, {%8,%9}, {%0,%1,%2,%3};"
        : "+f"(c[0]), "+f"(c[1]), "+f"(c[2]), "+f"(c[3])
        : "r"(a[0]), "r"(a[1]), "r"(a[2]), "r"(a[3]), "r"(b[0]), "r"(b[1]));
}

// ---------------- prep kernels ----------------
__global__ void f32_to_f16_kernel(const float4* __restrict__ in,
                                  uint4* __restrict__ out, int n8) {
    int i = blockIdx.x * blockDim.x + threadIdx.x;
    if (i < n8) {
        float4 a = in[2 * i], b = in[2 * i + 1];
        __half2 h0 = __floats2half2_rn(a.x, a.y);
        __half2 h1 = __floats2half2_rn(a.z, a.w);
        __half2 h2 = __floats2half2_rn(b.x, b.y);
        __half2 h3 = __floats2half2_rn(b.z, b.w);
        uint4 o;
        o.x = *(uint32_t*)&h0; o.y = *(uint32_t*)&h1;
        o.z = *(uint32_t*)&h2; o.w = *(uint32_t*)&h3;
        out[i] = o;
    }
}

__global__ void transpose_f16_kernel(const float* __restrict__ in,
                                     __half* __restrict__ out, int R, int C) {
    __shared__ float t[32][33];
    const int c0 = blockIdx.x * 32, r0 = blockIdx.y * 32;
    const int tx = threadIdx.x, ty = threadIdx.y;
    #pragma unroll
    for (int i = 0; i < 32; i += 8)
        t[ty + i][tx] = in[(size_t)(r0 + ty + i) * C + c0 + tx];
    __syncthreads();
    #pragma unroll
    for (int i = 0; i < 32; i += 8)
        out[(size_t)(c0 + ty + i) * R + r0 + tx] = __float2half_rn(t[tx][ty + i]);
}

// ---------------- fp16 mma.sync GEMM ----------------
// CTA 128x128, BK=64, 3 stages, 8 warps (4m x 2n), warp tile 32x64.
#define HLD 72
#define HTILE_B (128 * HLD * 2)
#define HSTAGE_B (2 * HTILE_B)
#define HSTAGES 3
#define GEMM_SMEM (HSTAGES * HSTAGE_B)           // 110592

__global__ void __launch_bounds__(256, 2)
gemm_f16_kernel(const __half* __restrict__ A, const __half* __restrict__ BT,
                void* __restrict__ Cv, const float* __restrict__ bias,
                int M, int N, int K, int out_half)
{
    extern __shared__ __half hsm[];
    const uint32_t sbase = smem_u32(hsm);

    const int tid = threadIdx.x;
    const int wid = tid >> 5, lane = tid & 31;
    const int wm = wid >> 1;
    const int wn = wid & 1;
    const int g = lane >> 2, t = lane & 3;
    const int q = lane >> 3, rl = lane & 7;
    const int m0 = blockIdx.y * 128, n0 = blockIdx.x * 128;

    const __half* Ab = A + (size_t)m0 * K;
    const __half* Bb = BT + (size_t)n0 * K;
    const int NC = K / 64;

    auto load_chunk = [&](int k0, int slot) {
        const uint32_t st = sbase + (uint32_t)(slot * HSTAGE_B);
        const uint32_t bb = st + HTILE_B;
        #pragma unroll
        for (int i = 0; i < 4; i++) {
            int idx = tid + i * 256;
            int r = idx >> 3, c16 = idx & 7;
            cpa16(st + (uint32_t)(r * 144 + c16 * 16),
                  Ab + (size_t)r * K + k0 + c16 * 8);
            cpa16(bb + (uint32_t)(r * 144 + c16 * 16),
                  Bb + (size_t)r * K + k0 + c16 * 8);
        }
    };

    uint32_t aoff[2], boff[4];
    #pragma unroll
    for (int mt = 0; mt < 2; mt++)
        aoff[mt] = (uint32_t)((wm * 32 + mt * 16 + (q & 1) * 8 + rl) * 144 +
                              (q >> 1) * 16);
    #pragma unroll
    for (int j = 0; j < 4; j++)
        boff[j] = (uint32_t)((wn * 64 + (2 * j + (q >> 1)) * 8 + rl) * 144 +
                             (q & 1) * 16) + HTILE_B;

    float acc[2][8][4];
    #pragma unroll
    for (int i = 0; i < 2; i++)
        #pragma unroll
        for (int j = 0; j < 8; j++)
            #pragma unroll
            for (int r = 0; r < 4; r++) acc[i][j][r] = 0.f;

    load_chunk(0, 0); CP_COMMIT();
    load_chunk(64, 1); CP_COMMIT();

    int slot_use = 0, slot_load = 2;
    for (int c = 0; c < NC; c++) {
        CP_WAIT(1);
        __syncthreads();
        if (c + 2 < NC) {
            load_chunk((c + 2) * 64, slot_load);
            slot_load = (slot_load + 1 == HSTAGES) ? 0 : slot_load + 1;
        }
        CP_COMMIT();

        const uint32_t st = sbase + (uint32_t)(slot_use * HSTAGE_B);
        slot_use = (slot_use + 1 == HSTAGES) ? 0 : slot_use + 1;

        #pragma unroll
        for (int ks = 0; ks < 4; ks++) {
            const uint32_t kadd = st + ks * 32;
            uint32_t a[2][4];
            ldsm4(a[0][0], a[0][1], a[0][2], a[0][3], kadd + aoff[0]);
            ldsm4(a[1][0], a[1][1], a[1][2], a[1][3], kadd + aoff[1]);
            #pragma unroll
            for (int j = 0; j < 4; j++) {
                uint32_t b0, b1, b2, b3;
                ldsm4(b0, b1, b2, b3, kadd + boff[j]);
                uint32_t be[2] = { b0, b1 }, bo[2] = { b2, b3 };
                mma_f16(acc[0][2 * j],     a[0], be);
                mma_f16(acc[1][2 * j],     a[1], be);
                mma_f16(acc[0][2 * j + 1], a[0], bo);
                mma_f16(acc[1][2 * j + 1], a[1], bo);
            }
        }
    }

    if (out_half) {
        __half* Cb = (__half*)Cv + (size_t)m0 * N + n0;
        #pragma unroll
        for (int mt = 0; mt < 2; mt++) {
            const int r0 = wm * 32 + mt * 16 + g;
            #pragma unroll
            for (int nt = 0; nt < 8; nt++) {
                const int col = wn * 64 + nt * 8 + t * 2;
                *(__half2*)(Cb + (size_t)r0 * N + col) =
                    __floats2half2_rn(acc[mt][nt][0], acc[mt][nt][1]);
                *(__half2*)(Cb + (size_t)(r0 + 8) * N + col) =
                    __floats2half2_rn(acc[mt][nt][2], acc[mt][nt][3]);
            }
        }
    } else {
        float* Cb = (float*)Cv + (size_t)m0 * N + n0;
        #pragma unroll
        for (int mt = 0; mt < 2; mt++) {
            const int r0 = wm * 32 + mt * 16 + g;
            #pragma unroll
            for (int nt = 0; nt < 8; nt++) {
                const int col = wn * 64 + nt * 8 + t * 2;
                float b0 = 0.f, b1 = 0.f;
                if (bias) { b0 = bias[n0 + col]; b1 = bias[n0 + col + 1]; }
                *(float2*)(Cb + (size_t)r0 * N + col) =
                    make_float2(acc[mt][nt][0] + b0, acc[mt][nt][1] + b1);
                *(float2*)(Cb + (size_t)(r0 + 8) * N + col) =
                    make_float2(acc[mt][nt][2] + b0, acc[mt][nt][3] + b1);
            }
        }
    }
}

// ---------------------------------------------------------------------------
// Banded flash attention, full fp16 MMA path.
// CTA = 64 queries x (head,batch); 4 warps; warp w owns query rows 16w..16w+15.
// SMEM (halves, 72/row): Q | K[3 stages] | V[3 stages] | P.  73728 bytes.
// ---------------------------------------------------------------------------
#define AHL 72
#define ABUF (64 * AHL * 2)              // 9216 bytes per buffer
#define ATT_SMEM (8 * ABUF)              // 73728

__global__ void __launch_bounds__(128) attn_f16_kernel(
    const __half* __restrict__ qkvh, __half* __restrict__ out)
{
    extern __shared__ __half hs[];
    const uint32_t sb = smem_u32(hs);
    const uint32_t sQ = sb;
    const uint32_t sK = sb + ABUF;           // 3 stages
    const uint32_t sV = sb + 4 * ABUF;       // 3 stages
    const uint32_t sP = sb + 7 * ABUF;

    const int tid = threadIdx.x;
    const int w = tid >> 5, lane = tid & 31;
    const int g = lane >> 2, t = lane & 3;
    const int q = lane >> 3, rl = lane & 7;
    const int n0 = blockIdx.x * 64;
    const int h  = blockIdx.y;
    const int b  = blockIdx.z;
    const float scale = 0.125f;

    const __half* base = qkvh + (size_t)b * SEQ * 3 * DM + h * HD;

    const int jlo = max(0, n0 - HALF);
    const int jhi = min(SEQ, n0 + 64 + HALF);
    const int NT = (jhi - jlo) >> 6;

    // loaders: 64 rows x 128B per operand, 512 chunks, 4/thread
    auto load_rows = [&](uint32_t dst, int j0, int sel) {
        #pragma unroll
        for (int i = 0; i < 4; i++) {
            int idx = tid + i * 128;
            int r = idx >> 3, c16 = idx & 7;
            cpa16(dst + (uint32_t)(r * 144 + c16 * 16),
                  base + (size_t)(j0 + r) * 3 * DM + sel * DM + c16 * 8);
        }
    };

    // prologue: Q + K0/V0, then K1/V1
    load_rows(sQ, n0, 0);
    load_rows(sK, jlo, 1);
    load_rows(sV, jlo, 2);
    CP_COMMIT();
    if (1 < NT) {
        load_rows(sK + ABUF, jlo + 64, 1);
        load_rows(sV + ABUF, jlo + 64, 2);
    }
    CP_COMMIT();

    // ldmatrix lane offsets (bytes)
    const uint32_t aoff = (uint32_t)((16 * w + (q & 1) * 8 + rl) * 144 +
                                     (q >> 1) * 16);
    uint32_t boffK[4], vboff[4];
    #pragma unroll
    for (int jt = 0; jt < 4; jt++)
        boffK[jt] = (uint32_t)(((2 * jt + (q >> 1)) * 8 + rl) * 144 +
                               (q & 1) * 16);
    #pragma unroll
    for (int dt = 0; dt < 4; dt++)
        vboff[dt] = (uint32_t)(((q & 1) * 8 + rl) * 144 + dt * 32 +
                               (q >> 1) * 16);

    float o[8][4];
    #pragma unroll
    for (int dt = 0; dt < 8; dt++)
        #pragma unroll
        for (int r = 0; r < 4; r++) o[dt][r] = 0.f;
    float m0 = -INFINITY, m1 = -INFINITY, l0 = 0.f, l1 = 0.f;

    const int i0 = n0 + w * 16 + g;
    const int i1 = i0 + 8;
    const int rowP0 = (16 * w + g) * AHL;

    int slot = 0, slot_load = 2;
    for (int c = 0; c < NT; c++) {
        const int j0 = jlo + c * 64;
        CP_WAIT(1);
        __syncthreads();
        if (c + 2 < NT) {
            load_rows(sK + slot_load * ABUF, j0 + 128, 1);
            load_rows(sV + slot_load * ABUF, j0 + 128, 2);
            slot_load = (slot_load + 1 == 3) ? 0 : slot_load + 1;
        }
        CP_COMMIT();

        const uint32_t kslot = sK + slot * ABUF;
        const uint32_t vslot = sV + slot * ABUF;
        slot = (slot + 1 == 3) ? 0 : slot + 1;

        // ---- S = Q @ K^T (fp16 MMA) ----
        float s[8][4];
        #pragma unroll
        for (int nt = 0; nt < 8; nt++)
            #pragma unroll
            for (int r = 0; r < 4; r++) s[nt][r] = 0.f;

        #pragma unroll
        for (int ks = 0; ks < 4; ks++) {
            uint32_t a[4];
            ldsm4(a[0], a[1], a[2], a[3], sQ + aoff + ks * 32);
            #pragma unroll
            for (int jt = 0; jt < 4; jt++) {
                uint32_t b0, b1, b2, b3;
                ldsm4(b0, b1, b2, b3, kslot + boffK[jt] + ks * 32);
                uint32_t be[2] = { b0, b1 }, bo[2] = { b2, b3 };
                mma_f16(s[2 * jt], a, be);
                mma_f16(s[2 * jt + 1], a, bo);
            }
        }

        // ---- scale + mask + online softmax ----
        const bool masked = (j0 - n0 == HALF) || (n0 - j0 == HALF);
        #pragma unroll
        for (int nt = 0; nt < 8; nt++) {
            #pragma unroll
            for (int r = 0; r < 4; r++) s[nt][r] *= scale;
            if (masked) {
                const int jc = j0 + 8 * nt + 2 * t;
                if (abs(i0 - jc) > HALF)       s[nt][0] = -INFINITY;
                if (abs(i0 - (jc + 1)) > HALF) s[nt][1] = -INFINITY;
                if (abs(i1 - jc) > HALF)       s[nt][2] = -INFINITY;
                if (abs(i1 - (jc + 1)) > HALF) s[nt][3] = -INFINITY;
            }
        }
        float mx0 = -INFINITY, mx1 = -INFINITY;
        #pragma unroll
        for (int nt = 0; nt < 8; nt++) {
            mx0 = fmaxf(mx0, fmaxf(s[nt][0], s[nt][1]));
            mx1 = fmaxf(mx1, fmaxf(s[nt][2], s[nt][3]));
        }
        mx0 = fmaxf(mx0, __shfl_xor_sync(0xffffffffu, mx0, 1));
        mx0 = fmaxf(mx0, __shfl_xor_sync(0xffffffffu, mx0, 2));
        mx1 = fmaxf(mx1, __shfl_xor_sync(0xffffffffu, mx1, 1));
        mx1 = fmaxf(mx1, __shfl_xor_sync(0xffffffffu, mx1, 2));
        const float nm0 = fmaxf(m0, mx0), nm1 = fmaxf(m1, mx1);
        const float corr0 = __expf(m0 - nm0), corr1 = __expf(m1 - nm1);
        m0 = nm0; m1 = nm1;

        float sum0 = 0.f, sum1 = 0.f;
        __half* Ph = hs + (sP - sb) / 2;
        #pragma unroll
        for (int nt = 0; nt < 8; nt++) {
            s[nt][0] = __expf(s[nt][0] - nm0);
            s[nt][1] = __expf(s[nt][1] - nm0);
            s[nt][2] = __expf(s[nt][2] - nm1);
            s[nt][3] = __expf(s[nt][3] - nm1);
            sum0 += s[nt][0] + s[nt][1];
            sum1 += s[nt][2] + s[nt][3];
            const int pc = rowP0 + 8 * nt + 2 * t;
            *(__half2*)(Ph + pc) = __floats2half2_rn(s[nt][0], s[nt][1]);
            *(__half2*)(Ph + pc + 8 * AHL) = __floats2half2_rn(s[nt][2], s[nt][3]);
        }
        sum0 += __shfl_xor_sync(0xffffffffu, sum0, 1);
        sum0 += __shfl_xor_sync(0xffffffffu, sum0, 2);
        sum1 += __shfl_xor_sync(0xffffffffu, sum1, 1);
        sum1 += __shfl_xor_sync(0xffffffffu, sum1, 2);
        l0 = l0 * corr0 + sum0;
        l1 = l1 * corr1 + sum1;
        #pragma unroll
        for (int dt = 0; dt < 8; dt++) {
            o[dt][0] *= corr0; o[dt][1] *= corr0;
            o[dt][2] *= corr1; o[dt][3] *= corr1;
        }
        __syncwarp();

        // ---- O += P @ V (fp16 MMA; V^T fragments via ldmatrix.trans) ----
        #pragma unroll
        for (int ks = 0; ks < 4; ks++) {
            uint32_t a[4];
            ldsm4(a[0], a[1], a[2], a[3], sP + aoff + ks * 32);
            #pragma unroll
            for (int dt = 0; dt < 4; dt++) {
                uint32_t r0, r1, r2, r3;
                ldsm4t(r0, r1, r2, r3, vslot + vboff[dt] + ks * 16 * 144);
                uint32_t be[2] = { r0, r1 }, bo[2] = { r2, r3 };
                mma_f16(o[2 * dt], a, be);
                mma_f16(o[2 * dt + 1], a, bo);
            }
        }
    }

    // epilogue: normalize + fp16 store
    const float inv0 = 1.f / l0, inv1 = 1.f / l1;
    __half* o0 = out + ((size_t)(b * SEQ + i0)) * DM + h * HD;
    __half* o1 = o0 + (size_t)8 * DM;
    #pragma unroll
    for (int dt = 0; dt < 8; dt++) {
        const int col = 8 * dt + 2 * t;
        *(__half2*)(o0 + col) = __floats2half2_rn(o[dt][0] * inv0,
                                                  o[dt][1] * inv0);
        *(__half2*)(o1 + col) = __floats2half2_rn(o[dt][2] * inv1,
                                                  o[dt][3] * inv1);
    }
}

// ---------------------------------------------------------------------------
extern "C" void kernel_launch(void* const* d_in, const int* in_sizes, int n_in,
                              void* d_out, int out_size)
{
    const float* x     = (const float*)d_in[0];
    const float* Wqkv  = (const float*)d_in[1];
    const float* Wproj = (const float*)d_in[2];
    const float* bproj = (const float*)d_in[3];
    float* out = (float*)d_out;

    __half *qkvh, *attnh, *xh, *wqkvTh, *wprojTh;
    cudaGetSymbolAddress((void**)&qkvh, g_qkvh);
    cudaGetSymbolAddress((void**)&attnh, g_attnh);
    cudaGetSymbolAddress((void**)&xh, g_xh);
    cudaGetSymbolAddress((void**)&wqkvTh, g_wqkvTh);
    cudaGetSymbolAddress((void**)&wprojTh, g_wprojTh);

    const int M = BATCH * SEQ;
    cudaFuncSetAttribute(attn_f16_kernel,
                         cudaFuncAttributeMaxDynamicSharedMemorySize,
                         ATT_SMEM);
    cudaFuncSetAttribute(gemm_f16_kernel,
                         cudaFuncAttributeMaxDynamicSharedMemorySize,
                         GEMM_SMEM);

    // 0) prep: convert x and transposed weights to fp16
    {
        const int n8 = M * DM / 8;
        f32_to_f16_kernel<<<(n8 + 255) / 256, 256>>>(
            (const float4*)x, (uint4*)xh, n8);
        dim3 tb(32, 8);
        transpose_f16_kernel<<<dim3(3 * DM / 32, DM / 32), tb>>>(
            Wqkv, wqkvTh, DM, 3 * DM);
        transpose_f16_kernel<<<dim3(DM / 32, DM / 32), tb>>>(
            Wproj, wprojTh, DM, DM);
    }
    // 1) QKV projection -> fp16 qkv
    {
        dim3 grid(3 * DM / 128, M / 128);
        gemm_f16_kernel<<<grid, 256, GEMM_SMEM>>>(xh, wqkvTh, qkvh, nullptr,
                                                  M, 3 * DM, DM, 1);
    }
    // 2) banded attention (fp16 tensor cores) -> fp16
    {
        dim3 grid(SEQ / 64, NH, BATCH);
        attn_f16_kernel<<<grid, 128, ATT_SMEM>>>(qkvh, attnh);
    }
    // 3) output projection + bias -> fp32
    {
        dim3 grid(DM / 128, M / 128);
        gemm_f16_kernel<<<grid, 256, GEMM_SMEM>>>(attnh, wprojTh, out, bproj,
                                                  M, DM, DM, 0);
    }
}